// round 10
// baseline (speedup 1.0000x reference)
#include <cuda_runtime.h>
#include <cstdint>

// Problem constants (from reference setup_inputs)
constexpr int F    = 128;    // n_latent = n_dim
constexpr int HID  = 256;    // hidden
constexpr int NMAX = 50000;
constexpr int EMAX = 800000;
constexpr int NBMAX = 64;    // max scan blocks (cdiv(50000,1024)=49)

// ---------------------------------------------------------------------------
// Consolidated scratch
// ---------------------------------------------------------------------------
constexpr size_t OFF_CNT  = 0;                      // [NMAX]
constexpr size_t OFF_CUR  = NMAX;                   // [NMAX]
constexpr size_t OFF_ROW  = 2 * (size_t)NMAX;       // [NMAX+1]
constexpr size_t OFF_BSUM = 3 * (size_t)NMAX + 1;   // [NBMAX]
constexpr size_t OFF_SRC  = OFF_BSUM + NBMAX;       // [EMAX]
constexpr size_t INT_TOTAL = OFF_SRC + EMAX;

constexpr size_t OFF_ENORM = 0;                              // [EMAX]
constexpr size_t OFF_DINV  = EMAX;                           // [NMAX]
constexpr size_t OFF_AX    = OFF_DINV + NMAX;                // [NMAX*F]
constexpr size_t OFF_Z1    = OFF_AX + (size_t)NMAX * F;      // [NMAX*HID]
constexpr size_t OFF_H2    = OFF_Z1 + (size_t)NMAX * HID;    // [NMAX*F]
constexpr size_t FLT_TOTAL = OFF_H2 + (size_t)NMAX * F;

__device__ int   g_int[INT_TOTAL];
__device__ float g_flt[FLT_TOTAL];

static inline int cdiv(int a, int b) { return (a + b - 1) / b; }

// ---------------------------------------------------------------------------
// CSR build  (edge_index int32: ei[0..E)=src, ei[E..2E)=dst)
// ---------------------------------------------------------------------------
__global__ void cnt_zero_kernel(int n) {
    int i = blockIdx.x * blockDim.x + threadIdx.x;
    if (i < n) g_int[OFF_CNT + i] = 0;
}

__global__ void cnt_count_kernel(const int* __restrict__ ei, int E, int N) {
    int e = blockIdx.x * blockDim.x + threadIdx.x;
    if (e < E) {
        int d = ei[(size_t)E + e];
        if (d >= 0 && d < N) atomicAdd(&g_int[OFF_CNT + d], 1);
    }
}

__global__ void dinv_kernel(int n) {
    int i = blockIdx.x * blockDim.x + threadIdx.x;
    if (i < n) g_flt[OFF_DINV + i] = rsqrtf((float)(g_int[OFF_CNT + i] + 1));
}

__global__ void __launch_bounds__(1024) blocksum_kernel(int n) {
    int t    = threadIdx.x;
    int lane = t & 31;
    int wid  = t >> 5;
    int i    = blockIdx.x * 1024 + t;
    int v    = (i < n) ? g_int[OFF_CNT + i] : 0;
#pragma unroll
    for (int off = 16; off > 0; off >>= 1)
        v += __shfl_down_sync(0xffffffffu, v, off);
    __shared__ int ws[32];
    if (lane == 0) ws[wid] = v;
    __syncthreads();
    if (wid == 0) {
        int u = ws[lane];
#pragma unroll
        for (int off = 16; off > 0; off >>= 1)
            u += __shfl_down_sync(0xffffffffu, u, off);
        if (lane == 0) g_int[OFF_BSUM + blockIdx.x] = u;
    }
}

__global__ void __launch_bounds__(64) bbase_kernel(int nb, int n) {
    __shared__ int sm[NBMAX];
    int t = threadIdx.x;
    if (t < nb) sm[t] = g_int[OFF_BSUM + t];
    __syncthreads();
    if (t == 0) {
        int run = 0;
        for (int i = 0; i < nb; i++) { int c = sm[i]; sm[i] = run; run += c; }
        g_int[OFF_ROW + n] = run;   // total E
    }
    __syncthreads();
    if (t < nb) g_int[OFF_BSUM + t] = sm[t];
}

__global__ void __launch_bounds__(1024) rowfill_kernel(int n) {
    int t    = threadIdx.x;
    int lane = t & 31;
    int wid  = t >> 5;
    int i    = blockIdx.x * 1024 + t;
    int v    = (i < n) ? g_int[OFF_CNT + i] : 0;

    int incl = v;
#pragma unroll
    for (int off = 1; off < 32; off <<= 1) {
        int u = __shfl_up_sync(0xffffffffu, incl, off);
        if (lane >= off) incl += u;
    }
    __shared__ int ws[32];
    if (lane == 31) ws[wid] = incl;
    __syncthreads();
    if (wid == 0) {
        int w = ws[lane];
#pragma unroll
        for (int off = 1; off < 32; off <<= 1) {
            int u = __shfl_up_sync(0xffffffffu, w, off);
            if (lane >= off) w += u;
        }
        ws[lane] = w;
    }
    __syncthreads();
    int warpbase = (wid == 0) ? 0 : ws[wid - 1];
    int excl = warpbase + incl - v;

    if (i < n) {
        g_int[OFF_ROW + i] = g_int[OFF_BSUM + blockIdx.x] + excl;
        g_int[OFF_CUR + i] = 0;
    }
}

__global__ void fill_kernel(const int* __restrict__ ei, int E, int N) {
    int e = blockIdx.x * blockDim.x + threadIdx.x;
    if (e >= E) return;
    int s = ei[e];
    int d = ei[(size_t)E + e];
    if (s < 0 || s >= N || d < 0 || d >= N) return;
    int pos = g_int[OFF_ROW + d] + atomicAdd(&g_int[OFF_CUR + d], 1);
    g_int[OFF_SRC + pos] = s;
    g_flt[OFF_ENORM + pos] = g_flt[OFF_DINV + s] * g_flt[OFF_DINV + d];
}

// ---------------------------------------------------------------------------
// Pull-mode aggregation: one warp per node, float4 lanes over F=128.
// ---------------------------------------------------------------------------
template <bool BIAS>
__device__ __forceinline__ void gather_body(const float* __restrict__ src_feat,
                                            float* __restrict__ dst_feat,
                                            const float* __restrict__ bias,
                                            int N) {
    int gid  = blockIdx.x * blockDim.x + threadIdx.x;
    int node = gid >> 5;
    int lane = gid & 31;
    if (node >= N) return;

    float dv = g_flt[OFF_DINV + node];
    float selfs = dv * dv;

    float4 v = ((const float4*)(src_feat + (size_t)node * F))[lane];
    float4 acc;
    acc.x = v.x * selfs;
    acc.y = v.y * selfs;
    acc.z = v.z * selfs;
    acc.w = v.w * selfs;
    if (BIAS) {
        float4 b = ((const float4*)bias)[lane];
        acc.x += b.x; acc.y += b.y; acc.z += b.z; acc.w += b.w;
    }

    int beg = g_int[OFF_ROW + node];
    int end = g_int[OFF_ROW + node + 1];
    for (int e = beg; e < end; e++) {
        int   s = g_int[OFF_SRC + e];
        float w = g_flt[OFF_ENORM + e];
        float4 u = ((const float4*)(src_feat + (size_t)s * F))[lane];
        acc.x = fmaf(u.x, w, acc.x);
        acc.y = fmaf(u.y, w, acc.y);
        acc.z = fmaf(u.z, w, acc.z);
        acc.w = fmaf(u.w, w, acc.w);
    }
    ((float4*)(dst_feat + (size_t)node * F))[lane] = acc;
}

__global__ void __launch_bounds__(256)
gather1_kernel(const float* __restrict__ x, int N) {
    gather_body<false>(x, &g_flt[OFF_AX], nullptr, N);
}

__global__ void __launch_bounds__(256)
gather2_kernel(float* __restrict__ out, const float* __restrict__ b2, int N) {
    gather_body<true>(&g_flt[OFF_H2], out, b2, N);
}

// ---------------------------------------------------------------------------
// TF32 tensor-core GEMM with 3-mma error compensation.
// C[M,NO] = A[M,K] @ W[K,NO] (+bias) (relu)
// Block 128x64, 256 threads (8 warps, 4m x 2n), warp tile 32x32, BK=16.
// A = Ah + Al, W = Wh + Wl (tf32 splits); C ≈ Ah@Wh + Al@Wh + Ah@Wl.
// ---------------------------------------------------------------------------
__device__ __forceinline__ uint32_t f2tf32(float x) {
    uint32_t r;
    asm("cvt.rna.tf32.f32 %0, %1;" : "=r"(r) : "f"(x));
    return r;
}

__device__ __forceinline__ void mma_tf32(float c[4], const uint32_t a[4],
                                         const uint32_t b[2]) {
    asm volatile(
        "mma.sync.aligned.m16n8k8.row.col.f32.tf32.tf32.f32 "
        "{%0,%1,%2,%3}, {%4,%5,%6,%7}, {%8,%9}, {%0,%1,%2,%3};"
        : "+f"(c[0]), "+f"(c[1]), "+f"(c[2]), "+f"(c[3])
        : "r"(a[0]), "r"(a[1]), "r"(a[2]), "r"(a[3]), "r"(b[0]), "r"(b[1]));
}

template <int K, int NO, bool RELU, bool BIAS>
__device__ __forceinline__ void gemm_tc_body(const float* __restrict__ A,
                                             const float* __restrict__ W,
                                             const float* __restrict__ bias,
                                             float* __restrict__ C, int M) {
    constexpr int BM = 128, BN = 64, BK = 16;
    __shared__ uint32_t As[2][BK][BM + 4];   // [hi/lo][k][m]
    __shared__ uint32_t Ws[2][BK][BN + 4];   // [hi/lo][k][n]

    int t    = threadIdx.x;
    int lane = t & 31;
    int wid  = t >> 5;
    int warp_m = wid & 3;    // 0..3, 32 rows each
    int warp_n = wid >> 2;   // 0..1, 32 cols each
    int g    = lane >> 2;    // 0..7
    int tig  = lane & 3;     // 0..3

    int r0 = blockIdx.x * BM;
    int c0 = blockIdx.y * BN;

    float c[2][4][4];
#pragma unroll
    for (int mt = 0; mt < 2; mt++)
#pragma unroll
        for (int nt = 0; nt < 4; nt++)
#pragma unroll
            for (int q = 0; q < 4; q++) c[mt][nt][q] = 0.f;

    // Load mappings
    int arow = t >> 2;       // 0..63 (+64 second iter)
    int aq   = t & 3;        // float4 group within BK=16
    int wr   = t >> 4;       // 0..15 (k)
    int wc   = t & 15;       // float4 group within BN=64

    for (int kk = 0; kk < K; kk += BK) {
        // --- A tile: 128 rows x 16 k, split hi/lo, stored k-major ---
#pragma unroll
        for (int it = 0; it < 2; it++) {
            int row = arow + it * 64;
            int gr  = r0 + row;
            float4 v = make_float4(0.f, 0.f, 0.f, 0.f);
            if (gr < M) v = *(const float4*)(A + (size_t)gr * K + kk + aq * 4);
            float vv[4] = {v.x, v.y, v.z, v.w};
#pragma unroll
            for (int j = 0; j < 4; j++) {
                uint32_t hb = f2tf32(vv[j]);
                float    lo = vv[j] - __uint_as_float(hb);
                As[0][aq * 4 + j][row] = hb;
                As[1][aq * 4 + j][row] = f2tf32(lo);
            }
        }
        // --- W tile: 16 k x 64 n, split hi/lo ---
        {
            float4 v = *(const float4*)(W + (size_t)(kk + wr) * NO + c0 + wc * 4);
            float vv[4] = {v.x, v.y, v.z, v.w};
#pragma unroll
            for (int j = 0; j < 4; j++) {
                uint32_t hb = f2tf32(vv[j]);
                float    lo = vv[j] - __uint_as_float(hb);
                Ws[0][wr][wc * 4 + j] = hb;
                Ws[1][wr][wc * 4 + j] = f2tf32(lo);
            }
        }
        __syncthreads();

#pragma unroll
        for (int ks = 0; ks < BK; ks += 8) {
            uint32_t ah[2][4], al[2][4];
#pragma unroll
            for (int mt = 0; mt < 2; mt++) {
                int rb = warp_m * 32 + mt * 16;
                ah[mt][0] = As[0][ks + tig][rb + g];
                ah[mt][1] = As[0][ks + tig][rb + g + 8];
                ah[mt][2] = As[0][ks + tig + 4][rb + g];
                ah[mt][3] = As[0][ks + tig + 4][rb + g + 8];
                al[mt][0] = As[1][ks + tig][rb + g];
                al[mt][1] = As[1][ks + tig][rb + g + 8];
                al[mt][2] = As[1][ks + tig + 4][rb + g];
                al[mt][3] = As[1][ks + tig + 4][rb + g + 8];
            }
            uint32_t bh[4][2], bl[4][2];
#pragma unroll
            for (int nt = 0; nt < 4; nt++) {
                int cb = warp_n * 32 + nt * 8;
                bh[nt][0] = Ws[0][ks + tig][cb + g];
                bh[nt][1] = Ws[0][ks + tig + 4][cb + g];
                bl[nt][0] = Ws[1][ks + tig][cb + g];
                bl[nt][1] = Ws[1][ks + tig + 4][cb + g];
            }
#pragma unroll
            for (int mt = 0; mt < 2; mt++)
#pragma unroll
                for (int nt = 0; nt < 4; nt++) {
                    mma_tf32(c[mt][nt], ah[mt], bh[nt]);
                    mma_tf32(c[mt][nt], al[mt], bh[nt]);
                    mma_tf32(c[mt][nt], ah[mt], bl[nt]);
                }
        }
        __syncthreads();
    }

    // Epilogue: c0,c1 -> row (g), cols 2*tig,2*tig+1; c2,c3 -> row g+8.
#pragma unroll
    for (int nt = 0; nt < 4; nt++) {
        int col = c0 + warp_n * 32 + nt * 8 + 2 * tig;
        float b0 = 0.f, b1 = 0.f;
        if (BIAS) { b0 = bias[col]; b1 = bias[col + 1]; }
#pragma unroll
        for (int mt = 0; mt < 2; mt++) {
            int rbase = r0 + warp_m * 32 + mt * 16 + g;
#pragma unroll
            for (int h = 0; h < 2; h++) {
                int row = rbase + h * 8;
                if (row < M) {
                    float o0 = c[mt][nt][h * 2 + 0] + b0;
                    float o1 = c[mt][nt][h * 2 + 1] + b1;
                    if (RELU) { o0 = fmaxf(o0, 0.f); o1 = fmaxf(o1, 0.f); }
                    *(float2*)(C + (size_t)row * NO + col) = make_float2(o0, o1);
                }
            }
        }
    }
}

__global__ void __launch_bounds__(256)
gemm1_kernel(const float* __restrict__ W1, const float* __restrict__ b1, int M) {
    gemm_tc_body<F, HID, true, true>(&g_flt[OFF_AX], W1, b1, &g_flt[OFF_Z1], M);
}

__global__ void __launch_bounds__(256)
gemm2_kernel(const float* __restrict__ W2, int M) {
    gemm_tc_body<HID, F, false, false>(&g_flt[OFF_Z1], W2, nullptr, &g_flt[OFF_H2], M);
}

// ---------------------------------------------------------------------------
// Launch — kernel launches ONLY (graph-capturable)
// ---------------------------------------------------------------------------
extern "C" void kernel_launch(void* const* d_in, const int* in_sizes, int n_in,
                              void* d_out, int out_size) {
    const float* x  = (const float*)d_in[0];
    const int*   ei = (const int*)d_in[1];     // int32 (harness converts int64)
    const float* W1 = (const float*)d_in[2];
    const float* b1 = (const float*)d_in[3];
    const float* W2 = (const float*)d_in[4];
    const float* b2 = (const float*)d_in[5];
    float*       out = (float*)d_out;

    int N = in_sizes[0] / F;
    int E = in_sizes[1] / 2;
    int NB = cdiv(N, 1024);

    // 1) CSR build + normalization
    cnt_zero_kernel<<<cdiv(N, 256), 256>>>(N);
    cnt_count_kernel<<<cdiv(E, 256), 256>>>(ei, E, N);
    dinv_kernel<<<cdiv(N, 256), 256>>>(N);
    blocksum_kernel<<<NB, 1024>>>(N);
    bbase_kernel<<<1, 64>>>(NB, N);
    rowfill_kernel<<<NB, 1024>>>(N);
    fill_kernel<<<cdiv(E, 256), 256>>>(ei, E, N);

    // 2) ax = agg(x)
    gather1_kernel<<<cdiv(N * 32, 256), 256>>>(x, N);

    // 3) z1 = relu(ax @ W1 + b1)    [N,128]@[128,256]
    {
        dim3 grid(cdiv(N, 128), HID / 64);
        gemm1_kernel<<<grid, 256>>>(W1, b1, N);
    }

    // 4) h2 = z1 @ W2               [N,256]@[256,128]
    {
        dim3 grid(cdiv(N, 128), F / 64);
        gemm2_kernel<<<grid, 256>>>(W2, N);
    }

    // 5) out = b2 + agg(h2)
    gather2_kernel<<<cdiv(N * 32, 256), 256>>>(out, b2, N);
}

// round 11
// speedup vs baseline: 1.4821x; 1.4821x over previous
#include <cuda_runtime.h>
#include <cuda_bf16.h>
#include <cstdint>

// Problem constants (from reference setup_inputs)
constexpr int F    = 128;    // n_latent = n_dim
constexpr int HID  = 256;    // hidden
constexpr int NMAX = 50000;
constexpr int EMAX = 800000;
constexpr int NBMAX = 64;    // max scan blocks (cdiv(50000,1024)=49)

// ---------------------------------------------------------------------------
// Consolidated scratch
// ---------------------------------------------------------------------------
constexpr size_t OFF_CNT  = 0;                      // [NMAX]
constexpr size_t OFF_CUR  = NMAX;                   // [NMAX]
constexpr size_t OFF_ROW  = 2 * (size_t)NMAX;       // [NMAX+1]
constexpr size_t OFF_BSUM = 3 * (size_t)NMAX + 1;   // [NBMAX]
constexpr size_t OFF_SRC  = OFF_BSUM + NBMAX;       // [EMAX]
constexpr size_t INT_TOTAL = OFF_SRC + EMAX;

constexpr size_t OFF_ENORM = 0;                              // [EMAX]
constexpr size_t OFF_DINV  = EMAX;                           // [NMAX]
constexpr size_t OFF_AX    = OFF_DINV + NMAX;                // [NMAX*F]
constexpr size_t OFF_Z1    = OFF_AX + (size_t)NMAX * F;      // [NMAX*HID]
constexpr size_t OFF_H2    = OFF_Z1 + (size_t)NMAX * HID;    // [NMAX*F]
constexpr size_t FLT_TOTAL = OFF_H2 + (size_t)NMAX * F;

__device__ int   g_int[INT_TOTAL];
__device__ float g_flt[FLT_TOTAL];

static inline int cdiv(int a, int b) { return (a + b - 1) / b; }

// ---------------------------------------------------------------------------
// CSR build  (edge_index int32: ei[0..E)=src, ei[E..2E)=dst)
// ---------------------------------------------------------------------------
__global__ void cnt_zero_kernel(int n) {
    int i = blockIdx.x * blockDim.x + threadIdx.x;
    if (i < n) g_int[OFF_CNT + i] = 0;
}

__global__ void cnt_count_kernel(const int* __restrict__ ei, int E, int N) {
    int e = blockIdx.x * blockDim.x + threadIdx.x;
    if (e < E) {
        int d = ei[(size_t)E + e];
        if (d >= 0 && d < N) atomicAdd(&g_int[OFF_CNT + d], 1);
    }
}

__global__ void dinv_kernel(int n) {
    int i = blockIdx.x * blockDim.x + threadIdx.x;
    if (i < n) g_flt[OFF_DINV + i] = rsqrtf((float)(g_int[OFF_CNT + i] + 1));
}

__global__ void __launch_bounds__(1024) blocksum_kernel(int n) {
    int t    = threadIdx.x;
    int lane = t & 31;
    int wid  = t >> 5;
    int i    = blockIdx.x * 1024 + t;
    int v    = (i < n) ? g_int[OFF_CNT + i] : 0;
#pragma unroll
    for (int off = 16; off > 0; off >>= 1)
        v += __shfl_down_sync(0xffffffffu, v, off);
    __shared__ int ws[32];
    if (lane == 0) ws[wid] = v;
    __syncthreads();
    if (wid == 0) {
        int u = ws[lane];
#pragma unroll
        for (int off = 16; off > 0; off >>= 1)
            u += __shfl_down_sync(0xffffffffu, u, off);
        if (lane == 0) g_int[OFF_BSUM + blockIdx.x] = u;
    }
}

__global__ void __launch_bounds__(64) bbase_kernel(int nb, int n) {
    __shared__ int sm[NBMAX];
    int t = threadIdx.x;
    if (t < nb) sm[t] = g_int[OFF_BSUM + t];
    __syncthreads();
    if (t == 0) {
        int run = 0;
        for (int i = 0; i < nb; i++) { int c = sm[i]; sm[i] = run; run += c; }
        g_int[OFF_ROW + n] = run;   // total E
    }
    __syncthreads();
    if (t < nb) g_int[OFF_BSUM + t] = sm[t];
}

__global__ void __launch_bounds__(1024) rowfill_kernel(int n) {
    int t    = threadIdx.x;
    int lane = t & 31;
    int wid  = t >> 5;
    int i    = blockIdx.x * 1024 + t;
    int v    = (i < n) ? g_int[OFF_CNT + i] : 0;

    int incl = v;
#pragma unroll
    for (int off = 1; off < 32; off <<= 1) {
        int u = __shfl_up_sync(0xffffffffu, incl, off);
        if (lane >= off) incl += u;
    }
    __shared__ int ws[32];
    if (lane == 31) ws[wid] = incl;
    __syncthreads();
    if (wid == 0) {
        int w = ws[lane];
#pragma unroll
        for (int off = 1; off < 32; off <<= 1) {
            int u = __shfl_up_sync(0xffffffffu, w, off);
            if (lane >= off) w += u;
        }
        ws[lane] = w;
    }
    __syncthreads();
    int warpbase = (wid == 0) ? 0 : ws[wid - 1];
    int excl = warpbase + incl - v;

    if (i < n) {
        g_int[OFF_ROW + i] = g_int[OFF_BSUM + blockIdx.x] + excl;
        g_int[OFF_CUR + i] = 0;
    }
}

__global__ void fill_kernel(const int* __restrict__ ei, int E, int N) {
    int e = blockIdx.x * blockDim.x + threadIdx.x;
    if (e >= E) return;
    int s = ei[e];
    int d = ei[(size_t)E + e];
    if (s < 0 || s >= N || d < 0 || d >= N) return;
    int pos = g_int[OFF_ROW + d] + atomicAdd(&g_int[OFF_CUR + d], 1);
    g_int[OFF_SRC + pos] = s;
    g_flt[OFF_ENORM + pos] = g_flt[OFF_DINV + s] * g_flt[OFF_DINV + d];
}

// ---------------------------------------------------------------------------
// Pull-mode aggregation: one warp per node, float4 lanes over F=128.
// ---------------------------------------------------------------------------
template <bool BIAS>
__device__ __forceinline__ void gather_body(const float* __restrict__ src_feat,
                                            float* __restrict__ dst_feat,
                                            const float* __restrict__ bias,
                                            int N) {
    int gid  = blockIdx.x * blockDim.x + threadIdx.x;
    int node = gid >> 5;
    int lane = gid & 31;
    if (node >= N) return;

    float dv = g_flt[OFF_DINV + node];
    float selfs = dv * dv;

    float4 v = ((const float4*)(src_feat + (size_t)node * F))[lane];
    float4 acc;
    acc.x = v.x * selfs;
    acc.y = v.y * selfs;
    acc.z = v.z * selfs;
    acc.w = v.w * selfs;
    if (BIAS) {
        float4 b = ((const float4*)bias)[lane];
        acc.x += b.x; acc.y += b.y; acc.z += b.z; acc.w += b.w;
    }

    int beg = g_int[OFF_ROW + node];
    int end = g_int[OFF_ROW + node + 1];
    for (int e = beg; e < end; e++) {
        int   s = g_int[OFF_SRC + e];
        float w = g_flt[OFF_ENORM + e];
        float4 u = ((const float4*)(src_feat + (size_t)s * F))[lane];
        acc.x = fmaf(u.x, w, acc.x);
        acc.y = fmaf(u.y, w, acc.y);
        acc.z = fmaf(u.z, w, acc.z);
        acc.w = fmaf(u.w, w, acc.w);
    }
    ((float4*)(dst_feat + (size_t)node * F))[lane] = acc;
}

__global__ void __launch_bounds__(256)
gather1_kernel(const float* __restrict__ x, int N) {
    gather_body<false>(x, &g_flt[OFF_AX], nullptr, N);
}

__global__ void __launch_bounds__(256)
gather2_kernel(float* __restrict__ out, const float* __restrict__ b2, int N) {
    gather_body<true>(&g_flt[OFF_H2], out, b2, N);
}

// ---------------------------------------------------------------------------
// BF16 tensor-core GEMM with 3-mma error compensation (Ootomo-style).
// C[M,NO] = A[M,K] @ W[K,NO] (+bias) (relu)
// Block 128x64, 256 threads (8 warps, 4m x 2n), warp tile 32x32, BK=32.
// A = Ah + Al (bf16 split), W = Wh + Wl; C ≈ Ah@Wh + Al@Wh + Ah@Wl.
// mma.m16n8k16.bf16; k-pairs packed into u32 smem words:
//   pk[k2][m] = pack(bf16(v[2*k2]), bf16(v[2*k2+1]))   (low half = even k)
// Row strides ≡ 8 (mod 32) so the 4 tig-groups hit disjoint banks.
// ---------------------------------------------------------------------------
__device__ __forceinline__ uint32_t pack_bb(__nv_bfloat16 a, __nv_bfloat16 b) {
    return (uint32_t)__bfloat16_as_ushort(a) |
           ((uint32_t)__bfloat16_as_ushort(b) << 16);
}

__device__ __forceinline__ void mma_bf16(float c[4], const uint32_t a[4],
                                         const uint32_t b[2]) {
    asm volatile(
        "mma.sync.aligned.m16n8k16.row.col.f32.bf16.bf16.f32 "
        "{%0,%1,%2,%3}, {%4,%5,%6,%7}, {%8,%9}, {%0,%1,%2,%3};"
        : "+f"(c[0]), "+f"(c[1]), "+f"(c[2]), "+f"(c[3])
        : "r"(a[0]), "r"(a[1]), "r"(a[2]), "r"(a[3]), "r"(b[0]), "r"(b[1]));
}

template <int K, int NO, bool RELU, bool BIAS>
__device__ __forceinline__ void gemm_tc_body(const float* __restrict__ A,
                                             const float* __restrict__ W,
                                             const float* __restrict__ bias,
                                             float* __restrict__ C, int M) {
    constexpr int BM = 128, BN = 64, BK = 32;
    constexpr int K2 = BK / 2;            // 16 packed k-pair rows
    constexpr int AST = BM + 8;           // 136 ≡ 8 (mod 32)
    constexpr int WST = BN + 8;           // 72  ≡ 8 (mod 32)
    __shared__ uint32_t As[2][K2][AST];   // [hi/lo][k2][m]
    __shared__ uint32_t Ws[2][K2][WST];   // [hi/lo][k2][n]

    int t    = threadIdx.x;
    int lane = t & 31;
    int wid  = t >> 5;
    int warp_m = wid & 3;    // 0..3, 32 rows each
    int warp_n = wid >> 2;   // 0..1, 32 cols each
    int g    = lane >> 2;    // 0..7
    int tig  = lane & 3;     // 0..3

    int r0 = blockIdx.x * BM;
    int c0 = blockIdx.y * BN;

    float c[2][4][4];
#pragma unroll
    for (int mt = 0; mt < 2; mt++)
#pragma unroll
        for (int nt = 0; nt < 4; nt++)
#pragma unroll
            for (int q = 0; q < 4; q++) c[mt][nt][q] = 0.f;

    // Load mappings
    int arow = t >> 2;       // 0..63 (+64 for second row-half)
    int aq   = t & 3;        // float4 group within a 16-k half
    int wk2  = t >> 5;       // 0..7 (k2 base; +8 second half)
    int wn   = (t & 31) * 2; // 0..62 (2 n-columns per thread)

    for (int kk = 0; kk < K; kk += BK) {
        // --- A tile: 128 rows x 32 k, bf16 hi/lo split, k-pair packed ---
#pragma unroll
        for (int it = 0; it < 2; it++) {
            int row = arow + it * 64;
            int gr  = r0 + row;
#pragma unroll
            for (int kh = 0; kh < 2; kh++) {
                float4 v = make_float4(0.f, 0.f, 0.f, 0.f);
                if (gr < M)
                    v = *(const float4*)(A + (size_t)gr * K + kk + kh * 16 + aq * 4);
                float vv[4] = {v.x, v.y, v.z, v.w};
                __nv_bfloat16 h[4], l[4];
#pragma unroll
                for (int j = 0; j < 4; j++) {
                    h[j] = __float2bfloat16(vv[j]);
                    l[j] = __float2bfloat16(vv[j] - __bfloat162float(h[j]));
                }
                int k2b = kh * 8 + aq * 2;
                As[0][k2b + 0][row] = pack_bb(h[0], h[1]);
                As[0][k2b + 1][row] = pack_bb(h[2], h[3]);
                As[1][k2b + 0][row] = pack_bb(l[0], l[1]);
                As[1][k2b + 1][row] = pack_bb(l[2], l[3]);
            }
        }
        // --- W tile: 32 k x 64 n, packed along k ---
#pragma unroll
        for (int kh = 0; kh < 2; kh++) {
            int k2 = wk2 + kh * 8;
            const float* wp = W + (size_t)(kk + 2 * k2) * NO + c0 + wn;
            float2 e = *(const float2*)wp;          // k even, cols wn, wn+1
            float2 o = *(const float2*)(wp + NO);   // k odd
            __nv_bfloat16 he0 = __float2bfloat16(e.x);
            __nv_bfloat16 he1 = __float2bfloat16(e.y);
            __nv_bfloat16 ho0 = __float2bfloat16(o.x);
            __nv_bfloat16 ho1 = __float2bfloat16(o.y);
            Ws[0][k2][wn + 0] = pack_bb(he0, ho0);
            Ws[0][k2][wn + 1] = pack_bb(he1, ho1);
            Ws[1][k2][wn + 0] =
                pack_bb(__float2bfloat16(e.x - __bfloat162float(he0)),
                        __float2bfloat16(o.x - __bfloat162float(ho0)));
            Ws[1][k2][wn + 1] =
                pack_bb(__float2bfloat16(e.y - __bfloat162float(he1)),
                        __float2bfloat16(o.y - __bfloat162float(ho1)));
        }
        __syncthreads();

#pragma unroll
        for (int ks = 0; ks < K2; ks += 8) {     // two k16 mma steps
            uint32_t ah[2][4], al[2][4];
#pragma unroll
            for (int mt = 0; mt < 2; mt++) {
                int rb = warp_m * 32 + mt * 16;
                ah[mt][0] = As[0][ks + tig][rb + g];
                ah[mt][1] = As[0][ks + tig][rb + g + 8];
                ah[mt][2] = As[0][ks + tig + 4][rb + g];
                ah[mt][3] = As[0][ks + tig + 4][rb + g + 8];
                al[mt][0] = As[1][ks + tig][rb + g];
                al[mt][1] = As[1][ks + tig][rb + g + 8];
                al[mt][2] = As[1][ks + tig + 4][rb + g];
                al[mt][3] = As[1][ks + tig + 4][rb + g + 8];
            }
            uint32_t bh[4][2], bl[4][2];
#pragma unroll
            for (int nt = 0; nt < 4; nt++) {
                int cb = warp_n * 32 + nt * 8;
                bh[nt][0] = Ws[0][ks + tig][cb + g];
                bh[nt][1] = Ws[0][ks + tig + 4][cb + g];
                bl[nt][0] = Ws[1][ks + tig][cb + g];
                bl[nt][1] = Ws[1][ks + tig + 4][cb + g];
            }
#pragma unroll
            for (int mt = 0; mt < 2; mt++)
#pragma unroll
                for (int nt = 0; nt < 4; nt++) {
                    mma_bf16(c[mt][nt], ah[mt], bh[nt]);
                    mma_bf16(c[mt][nt], al[mt], bh[nt]);
                    mma_bf16(c[mt][nt], ah[mt], bl[nt]);
                }
        }
        __syncthreads();
    }

    // Epilogue: c0,c1 -> row g, cols 2tig,2tig+1; c2,c3 -> row g+8.
#pragma unroll
    for (int nt = 0; nt < 4; nt++) {
        int col = c0 + warp_n * 32 + nt * 8 + 2 * tig;
        float b0 = 0.f, b1 = 0.f;
        if (BIAS) { b0 = bias[col]; b1 = bias[col + 1]; }
#pragma unroll
        for (int mt = 0; mt < 2; mt++) {
            int rbase = r0 + warp_m * 32 + mt * 16 + g;
#pragma unroll
            for (int h = 0; h < 2; h++) {
                int row = rbase + h * 8;
                if (row < M) {
                    float o0 = c[mt][nt][h * 2 + 0] + b0;
                    float o1 = c[mt][nt][h * 2 + 1] + b1;
                    if (RELU) { o0 = fmaxf(o0, 0.f); o1 = fmaxf(o1, 0.f); }
                    *(float2*)(C + (size_t)row * NO + col) = make_float2(o0, o1);
                }
            }
        }
    }
}

__global__ void __launch_bounds__(256)
gemm1_kernel(const float* __restrict__ W1, const float* __restrict__ b1, int M) {
    gemm_tc_body<F, HID, true, true>(&g_flt[OFF_AX], W1, b1, &g_flt[OFF_Z1], M);
}

__global__ void __launch_bounds__(256)
gemm2_kernel(const float* __restrict__ W2, int M) {
    gemm_tc_body<HID, F, false, false>(&g_flt[OFF_Z1], W2, nullptr, &g_flt[OFF_H2], M);
}

// ---------------------------------------------------------------------------
// Launch — kernel launches ONLY (graph-capturable)
// ---------------------------------------------------------------------------
extern "C" void kernel_launch(void* const* d_in, const int* in_sizes, int n_in,
                              void* d_out, int out_size) {
    const float* x  = (const float*)d_in[0];
    const int*   ei = (const int*)d_in[1];     // int32 (harness converts int64)
    const float* W1 = (const float*)d_in[2];
    const float* b1 = (const float*)d_in[3];
    const float* W2 = (const float*)d_in[4];
    const float* b2 = (const float*)d_in[5];
    float*       out = (float*)d_out;

    int N = in_sizes[0] / F;
    int E = in_sizes[1] / 2;
    int NB = cdiv(N, 1024);

    // 1) CSR build + normalization
    cnt_zero_kernel<<<cdiv(N, 256), 256>>>(N);
    cnt_count_kernel<<<cdiv(E, 256), 256>>>(ei, E, N);
    dinv_kernel<<<cdiv(N, 256), 256>>>(N);
    blocksum_kernel<<<NB, 1024>>>(N);
    bbase_kernel<<<1, 64>>>(NB, N);
    rowfill_kernel<<<NB, 1024>>>(N);
    fill_kernel<<<cdiv(E, 256), 256>>>(ei, E, N);

    // 2) ax = agg(x)
    gather1_kernel<<<cdiv(N * 32, 256), 256>>>(x, N);

    // 3) z1 = relu(ax @ W1 + b1)    [N,128]@[128,256]
    {
        dim3 grid(cdiv(N, 128), HID / 64);
        gemm1_kernel<<<grid, 256>>>(W1, b1, N);
    }

    // 4) h2 = z1 @ W2               [N,256]@[256,128]
    {
        dim3 grid(cdiv(N, 128), F / 64);
        gemm2_kernel<<<grid, 256>>>(W2, N);
    }

    // 5) out = b2 + agg(h2)
    gather2_kernel<<<cdiv(N * 32, 256), 256>>>(out, b2, N);
}